// round 16
// baseline (speedup 1.0000x reference)
#include <cuda_runtime.h>
#include <cuda_fp16.h>
#include <math.h>
#include <mma.h>
#include <cstdint>

using namespace nvcuda;

// Problem dims
#define B_   2
#define T_   512
#define C_   768
#define H_   12
#define K_   64
#define L_   6
#define DFF_ 2688
#define V_   50304
#define M_   (B_*T_)   // 1024 rows

// weight family sizes (elements)
#define CCL  ((long)L_*C_*C_)
#define FCL  ((long)L_*DFF_*C_)
#define VCL  ((long)V_*C_)

#define OFF_WR   0L
#define OFF_WK   (OFF_WR + CCL)
#define OFF_WV   (OFF_WK + CCL)
#define OFF_WG   (OFF_WV + CCL)
#define OFF_WO   (OFF_WG + CCL)
#define OFF_WIN  (OFF_WO + CCL)
#define OFF_WOUT (OFF_WIN + FCL)
#define OFF_WGT  (OFF_WOUT + FCL)
#define OFF_WUN  (OFF_WGT + CCL)
#define WTF_TOT  (OFF_WUN + VCL)

// ---------------- scratch (device globals; no allocation allowed) ----------
__device__ __half g_wh  [WTF_TOT];    // fp16 weights
__device__ float  g_x   [M_*C_];
__device__ float  g_ln  [M_*C_];
__device__ __half g_ah  [4*M_*C_];    // half activations
__device__ __half g_hidh[M_*DFF_];    // half hidden (relu^2 out)
__device__ __half g_gath[M_*C_];      // half gated (gn*silu out)
__device__ float  g_part[4*M_*C_];    // split-K partials
__device__ float  g_rkvg[4*M_*C_];
__device__ float  g_wkv [M_*C_];
__device__ float  g_gate[M_*C_];

// ---------------- helpers ---------------------------------------------------
__device__ __forceinline__ void cp_async16(void* smem_dst, const void* gsrc) {
    unsigned dst = (unsigned)__cvta_generic_to_shared(smem_dst);
    asm volatile("cp.async.cg.shared.global [%0], [%1], 16;\n" :: "r"(dst), "l"(gsrc));
}
__device__ __forceinline__ void cp_commit() { asm volatile("cp.async.commit_group;\n"); }
__device__ __forceinline__ void cp_wait1()  { asm volatile("cp.async.wait_group 1;\n"); }
__device__ __forceinline__ void cp_wait0()  { asm volatile("cp.async.wait_group 0;\n"); }

// ---------------- batched fp32 -> fp16 weight conversion -------------------
struct CvtSeg { const float* src; long dst_off; long n8; };
struct CvtArgs5 { CvtSeg s[5]; int n; };

__global__ void cvt_all_kernel(CvtArgs5 args, __half* __restrict__ dstbase, long total8)
{
    long base = (long)blockIdx.x*1024 + threadIdx.x;

    const float4* src4[4];
    uint4*        dst4[4];
    bool          ok[4];
    #pragma unroll
    for (int it = 0; it < 4; it++) {
        long gid = base + (long)it*256;
        ok[it] = (gid < total8);
        src4[it] = nullptr; dst4[it] = nullptr;
        if (ok[it]) {
            long rem = gid;
            #pragma unroll
            for (int s = 0; s < 5; s++) {
                if (s >= args.n) { ok[it] = false; break; }
                if (rem < args.s[s].n8) {
                    src4[it] = (const float4*)args.s[s].src + 2*rem;
                    dst4[it] = (uint4*)(dstbase + args.s[s].dst_off) + rem;
                    break;
                }
                rem -= args.s[s].n8;
            }
        }
    }

    float4 a[4], b[4];
    #pragma unroll
    for (int it = 0; it < 4; it++) {
        if (ok[it]) { a[it] = src4[it][0]; b[it] = src4[it][1]; }
    }
    #pragma unroll
    for (int it = 0; it < 4; it++) {
        if (!ok[it]) continue;
        __half2 h0 = __floats2half2_rn(a[it].x, a[it].y);
        __half2 h1 = __floats2half2_rn(a[it].z, a[it].w);
        __half2 h2 = __floats2half2_rn(b[it].x, b[it].y);
        __half2 h3 = __floats2half2_rn(b[it].z, b[it].w);
        uint4 o;
        o.x = *(uint32_t*)&h0; o.y = *(uint32_t*)&h1;
        o.z = *(uint32_t*)&h2; o.w = *(uint32_t*)&h3;
        *dst4[it] = o;
    }
}

// ---------------- FP16 wmma GEMM, BK=32, cp.async double-buffered ----------
template<int BM, int BN, int WARPS, int WNW, int EPI, int SPLITK, int HOUT>
__global__ void __launch_bounds__(WARPS*32, (WARPS==4)?2:6)
hgemm(const __half* __restrict__ Abase,
      const __half* __restrict__ W0, const __half* __restrict__ W1,
      const __half* __restrict__ W2, const __half* __restrict__ W3,
      float* __restrict__ Cbase, __half* __restrict__ Chbase,
      const float* __restrict__ Res, const float* __restrict__ Gate,
      int M, int N, int Kseg, int lda)
{
    constexpr int NT  = WARPS*32;
    constexpr int BK  = 32;
    constexpr int LDT = 40;                    // halves; 80B rows
    extern __shared__ __align__(16) __half sh[];
    __half* As = sh;                           // [2][BM*LDT]
    __half* Bs = sh + 2*BM*LDT;                // [2][BN*LDT]
    __shared__ __align__(16) float Ep[(EPI >= 3 || HOUT) ? WARPS*256 : 8];

    int z = blockIdx.z;
    const __half* A;
    const __half* W;
    float*  C  = nullptr;
    __half* Ch = nullptr;
    if (SPLITK) {
        A = Abase + (size_t)z*Kseg;
        W = W0    + (size_t)z*Kseg;
        C = Cbase + (size_t)z*M*N;
    } else {
        A = Abase + (size_t)z*M*lda;
        W = W0;
        if (z == 1) W = W1; else if (z == 2) W = W2; else if (z == 3) W = W3;
        if (HOUT) Ch = Chbase + (size_t)z*M*N;
        else      C  = Cbase  + (size_t)z*M*N;
    }

    int bm = blockIdx.y*BM, bn = blockIdx.x*BN;
    int tid = threadIdx.x, warp = tid>>5, lane = tid&31;
    constexpr int WMW = WARPS / WNW;
    int wm = warp / WNW;
    int wn = warp % WNW;
    constexpr int WM = BM/WMW;
    constexpr int WN = BN/WNW;
    constexpr int MF = WM/16, NF = WN/16;

    wmma::fragment<wmma::accumulator,16,16,16,float> cf[MF][NF];
    #pragma unroll
    for (int i=0;i<MF;i++)
        #pragma unroll
        for (int j=0;j<NF;j++) wmma::fill_fragment(cf[i][j], 0.f);

    constexpr int A_CP = BM*(BK/8)/NT;
    constexpr int B_CP = BN*(BK/8)/NT;

    const int nK = Kseg / BK;

    auto issue_stage = [&](int stg, int kt) {
        int k0 = kt*BK;
        __half* as = As + stg*BM*LDT;
        __half* bs = Bs + stg*BN*LDT;
        #pragma unroll
        for (int i=0;i<A_CP;i++){
            int idx = tid + i*NT;
            int row = idx >> 2, c8 = idx & 3;
            cp_async16(&as[row*LDT + c8*8],
                       A + (size_t)(bm+row)*lda + k0 + c8*8);
        }
        #pragma unroll
        for (int i=0;i<B_CP;i++){
            int idx = tid + i*NT;
            int row = idx >> 2, c8 = idx & 3;
            cp_async16(&bs[row*LDT + c8*8],
                       W + (size_t)(bn+row)*lda + k0 + c8*8);
        }
        cp_commit();
    };

    issue_stage(0, 0);

    for (int kt = 0; kt < nK; kt++) {
        if (kt + 1 < nK) { issue_stage((kt+1)&1, kt+1); cp_wait1(); }
        else             { cp_wait0(); }
        __syncthreads();
        int stg = kt & 1;
        const __half* as = As + stg*BM*LDT;
        const __half* bs = Bs + stg*BN*LDT;
        #pragma unroll
        for (int kk=0; kk<BK; kk+=16) {
            wmma::fragment<wmma::matrix_a,16,16,16,__half,wmma::row_major> af[MF];
            #pragma unroll
            for (int i=0;i<MF;i++)
                wmma::load_matrix_sync(af[i], &as[(wm*WM + i*16)*LDT + kk], LDT);
            #pragma unroll
            for (int j=0;j<NF;j++) {
                wmma::fragment<wmma::matrix_b,16,16,16,__half,wmma::col_major> bf;
                wmma::load_matrix_sync(bf, &bs[(wn*WN + j*16)*LDT + kk], LDT);
                #pragma unroll
                for (int i=0;i<MF;i++)
                    wmma::mma_sync(cf[i][j], af[i], bf, cf[i][j]);
            }
        }
        __syncthreads();
    }

    // ---- epilogue ----
    #pragma unroll
    for (int i=0;i<MF;i++){
        #pragma unroll
        for (int j=0;j<NF;j++){
            int r0 = bm + wm*WM + i*16;
            int c0 = bn + wn*WN + j*16;
            if (!HOUT && EPI == 0) {
                wmma::store_matrix_sync(&C[(size_t)r0*N + c0], cf[i][j], N, wmma::mem_row_major);
            } else if (!HOUT && EPI == 2) {
                #pragma unroll
                for (int e=0;e<cf[i][j].num_elements;e++)
                    cf[i][j].x[e] = 1.f/(1.f + expf(-cf[i][j].x[e]));
                wmma::store_matrix_sync(&C[(size_t)r0*N + c0], cf[i][j], N, wmma::mem_row_major);
            } else {
                float* buf = &Ep[warp*256];
                wmma::store_matrix_sync(buf, cf[i][j], 16, wmma::mem_row_major);
                __syncwarp();
                #pragma unroll
                for (int e=0;e<8;e++){
                    int idx2 = lane*8 + e;
                    int rr = idx2>>4, cc2 = idx2&15;
                    size_t o = (size_t)(r0+rr)*N + (c0+cc2);
                    float v = buf[idx2];
                    if (EPI == 1) { v = fmaxf(v, 0.f); v = v*v; }
                    else if (EPI == 3) { v += Res[o]; }
                    else if (EPI == 4) { v = fmaf(v, Gate[o], Res[o]); }
                    if (HOUT) Ch[o] = __float2half_rn(v);
                    else      C[o]  = v;
                }
                __syncwarp();
            }
        }
    }
}

// ---------------- split-K reduce: x += (p0+p1+p2+p3) * gate ----------------
__global__ void reduce4_gate_kernel(const float* __restrict__ parts,
                                    const float* __restrict__ gate,
                                    float* __restrict__ x, int n)
{
    int idx = blockIdx.x*blockDim.x + threadIdx.x;
    if (idx >= n) return;
    float v = (parts[idx]               + parts[idx +   (size_t)n])
            + (parts[idx + 2*(size_t)n] + parts[idx + 3*(size_t)n]);
    x[idx] = fmaf(v, gate[idx], x[idx]);
}

// ---------------- plain LayerNorm (emb gather / head), single-pass stats ---
__global__ void ln_kernel(const float* __restrict__ in,
                          const int*   __restrict__ tokens,
                          float*       __restrict__ out,
                          __half*      __restrict__ hout,
                          const float* __restrict__ s,
                          const float* __restrict__ bia,
                          float eps)
{
    int row = blockIdx.x;
    const float* xp = tokens ? (in + (size_t)tokens[row]*C_)
                             : (in + (size_t)row*C_);
    int tid = threadIdx.x;
    float v0 = xp[tid], v1 = xp[tid+256], v2 = xp[tid+512];

    __shared__ float red1[8], red2[8];
    __shared__ float s_mean, s_rstd;

    float s1 = v0 + v1 + v2;
    float s2v = v0*v0 + v1*v1 + v2*v2;
    #pragma unroll
    for (int o=16;o;o>>=1) {
        s1  += __shfl_xor_sync(0xffffffffu, s1, o);
        s2v += __shfl_xor_sync(0xffffffffu, s2v, o);
    }
    if ((tid & 31) == 0) { red1[tid>>5] = s1; red2[tid>>5] = s2v; }
    __syncthreads();
    if (tid == 0) {
        float t1=0.f, t2=0.f;
        for (int i=0;i<8;i++) { t1 += red1[i]; t2 += red2[i]; }
        float m = t1*(1.f/C_);
        s_mean = m;
        s_rstd = rsqrtf(t2*(1.f/C_) - m*m + eps);
    }
    __syncthreads();
    float m  = s_mean, rs = s_rstd;
    float y0 = (v0-m)*rs*s[tid]     + bia[tid];
    float y1 = (v1-m)*rs*s[tid+256] + bia[tid+256];
    float y2 = (v2-m)*rs*s[tid+512] + bia[tid+512];
    if (hout) {
        __half* hp = hout + (size_t)row*C_;
        hp[tid]     = __float2half_rn(y0);
        hp[tid+256] = __float2half_rn(y1);
        hp[tid+512] = __float2half_rn(y2);
    } else {
        float* op = out + (size_t)row*C_;
        op[tid] = y0; op[tid+256] = y1; op[tid+512] = y2;
    }
}

// ---------------- fused LN + token-shift + N-way lerp, single-pass stats ---
template<int NOUT>
__global__ void ln_lerp_kernel(const float* __restrict__ x,
                               const float* __restrict__ s,
                               const float* __restrict__ bia,
                               const float* __restrict__ t0,
                               const float* __restrict__ t1,
                               const float* __restrict__ t2,
                               const float* __restrict__ t3,
                               __half* __restrict__ aout)
{
    int row = blockIdx.x;
    int t   = row % T_;
    int tid = threadIdx.x;                 // 256

    const float* xc = x + (size_t)row*C_;
    float c0 = xc[tid], c1 = xc[tid+256], c2 = xc[tid+512];
    float p0 = 0.f, p1 = 0.f, p2 = 0.f;
    if (t > 0) {
        const float* xq = xc - C_;
        p0 = xq[tid]; p1 = xq[tid+256]; p2 = xq[tid+512];
    }

    __shared__ float r1c[8], r2c[8], r1p[8], r2p[8];
    __shared__ float s_mc, s_rc, s_mp, s_rp;

    float sc  = c0 + c1 + c2;
    float qc  = c0*c0 + c1*c1 + c2*c2;
    float sp  = p0 + p1 + p2;
    float qp  = p0*p0 + p1*p1 + p2*p2;
    #pragma unroll
    for (int o=16;o;o>>=1) {
        sc += __shfl_xor_sync(0xffffffffu, sc, o);
        qc += __shfl_xor_sync(0xffffffffu, qc, o);
        sp += __shfl_xor_sync(0xffffffffu, sp, o);
        qp += __shfl_xor_sync(0xffffffffu, qp, o);
    }
    if ((tid & 31) == 0) {
        r1c[tid>>5] = sc; r2c[tid>>5] = qc;
        r1p[tid>>5] = sp; r2p[tid>>5] = qp;
    }
    __syncthreads();
    if (tid == 0) {
        float tsc=0.f, tqc=0.f, tsp=0.f, tqp=0.f;
        for (int i=0;i<8;i++) { tsc += r1c[i]; tqc += r2c[i];
                                tsp += r1p[i]; tqp += r2p[i]; }
        float mc = tsc*(1.f/C_), mp = tsp*(1.f/C_);
        s_mc = mc; s_mp = mp;
        s_rc = rsqrtf(tqc*(1.f/C_) - mc*mc + 1e-5f);
        s_rp = rsqrtf(tqp*(1.f/C_) - mp*mp + 1e-5f);
    }
    __syncthreads();
    float mc = s_mc, rc = s_rc, mp = s_mp, rp = s_rp;

    #pragma unroll
    for (int u = 0; u < 3; u++) {
        int c  = tid + u*256;
        float cv = (u==0)?c0:((u==1)?c1:c2);
        float pv = (u==0)?p0:((u==1)?p1:p2);
        float yc = (cv-mc)*rc*s[c] + bia[c];
        float yp = (t > 0) ? ((pv-mp)*rp*s[c] + bia[c]) : 0.f;
        float d  = yp - yc;
        size_t o = (size_t)row*C_ + c;
        aout[o]                       = __float2half_rn(fmaf(t0[c], d, yc));
        aout[o +   (size_t)M_*C_]     = __float2half_rn(fmaf(t1[c], d, yc));
        if (NOUT == 4) {
            aout[o + 2*(size_t)M_*C_] = __float2half_rn(fmaf(t2[c], d, yc));
            aout[o + 3*(size_t)M_*C_] = __float2half_rn(fmaf(t3[c], d, yc));
        }
    }
}

// ---------------- WKV scan: 256 thr, 8-way k-split, pair-unrolled ----------
__global__ void wkv_kernel(const float* __restrict__ r, const float* __restrict__ k,
                           const float* __restrict__ v, float* __restrict__ out,
                           const float* __restrict__ bonus, const float* __restrict__ decay)
{
    int blk  = blockIdx.x;
    int vs   = blk & 1;
    int h    = (blk >> 1) % H_;
    int b    = blk / (2*H_);
    int tid  = threadIdx.x;        // 256
    int kc   = tid & 7;
    int vloc = tid >> 3;           // 0..31
    int vg   = vs*32 + vloc;

    size_t off = (size_t)b*T_*C_ + (size_t)h*K_;
    const float* rp = r + off;
    const float* kp = k + off;
    const float* vp = v + off;
    float*       op = out + off;

    float u[8], w[8], st[8];
    #pragma unroll
    for (int i = 0; i < 8; i++) {
        int kk = kc*8 + i;
        u[i]  = bonus[h*K_ + kk];
        w[i]  = expf(-expf(decay[h*K_ + kk]));
        st[i] = 0.f;
    }

    __shared__ float shr[2][2][64], shk[2][2][64];

    {
        int seg = tid >> 6, idx = tid & 63;
        if      (seg == 0) shr[0][0][idx] = rp[idx];
        else if (seg == 1) shr[0][1][idx] = rp[C_ + idx];
        else if (seg == 2) shk[0][0][idx] = kp[idx];
        else               shk[0][1][idx] = kp[C_ + idx];
    }
    float vv0 = vp[vg];
    float vv1 = vp[C_ + vg];
    __syncthreads();

    const int NP = T_/2;
    for (int p = 0; p < NP; p++) {
        int cur = p & 1, nxt = cur ^ 1;
        int t0 = 2*p;

        float pre = 0.f, nv0 = 0.f, nv1 = 0.f;
        int seg = tid >> 6, idx = tid & 63;
        if (p + 1 < NP) {
            size_t oA = (size_t)(t0+2)*C_, oB = (size_t)(t0+3)*C_;
            if      (seg == 0) pre = rp[oA + idx];
            else if (seg == 1) pre = rp[oB + idx];
            else if (seg == 2) pre = kp[oA + idx];
            else               pre = kp[oB + idx];
            nv0 = vp[oA + vg];
            nv1 = vp[oB + vg];
        }

        {
            float acc0 = 0.f, acc1 = 0.f;
            #pragma unroll
            for (int i = 0; i < 8; i += 2) {
                float k0 = shk[cur][0][kc*8 + i]     * vv0;
                float k1 = shk[cur][0][kc*8 + i + 1] * vv0;
                acc0  = fmaf(shr[cur][0][kc*8 + i],     fmaf(u[i],   k0, st[i]),   acc0);
                acc1  = fmaf(shr[cur][0][kc*8 + i + 1], fmaf(u[i+1], k1, st[i+1]), acc1);
                st[i]   = fmaf(st[i],   w[i],   k0);
                st[i+1] = fmaf(st[i+1], w[i+1], k1);
            }
            float acc = acc0 + acc1;
            acc += __shfl_xor_sync(0xffffffffu, acc, 1);
            acc += __shfl_xor_sync(0xffffffffu, acc, 2);
            acc += __shfl_xor_sync(0xffffffffu, acc, 4);
            if (kc == 0) op[(size_t)t0*C_ + vg] = acc;
        }
        {
            float acc0 = 0.f, acc1 = 0.f;
            #pragma unroll
            for (int i = 0; i < 8; i += 2) {
                float k0 = shk[cur][1][kc*8 + i]     * vv1;
                float k1 = shk[cur][1][kc*8 + i + 1] * vv1;
                acc0  = fmaf(shr[cur][1][kc*8 + i],     fmaf(u[i],   k0, st[i]),   acc0);
                acc1  = fmaf(shr[cur][1][kc*8 + i + 1], fmaf(u[i+1], k1, st[i+1]), acc1);
                st[i]   = fmaf(st[i],   w[i],   k0);
                st[i+1] = fmaf(st[i+1], w[i+1], k1);
            }
            float acc = acc0 + acc1;
            acc += __shfl_xor_sync(0xffffffffu, acc, 1);
            acc += __shfl_xor_sync(0xffffffffu, acc, 2);
            acc += __shfl_xor_sync(0xffffffffu, acc, 4);
            if (kc == 0) op[(size_t)(t0+1)*C_ + vg] = acc;
        }

        if (p + 1 < NP) {
            if      (seg == 0) shr[nxt][0][idx] = pre;
            else if (seg == 1) shr[nxt][1][idx] = pre;
            else if (seg == 2) shk[nxt][0][idx] = pre;
            else               shk[nxt][1][idx] = pre;
            vv0 = nv0; vv1 = nv1;
        }
        __syncthreads();
    }
}

// ---------------- GroupNorm(H groups of 64) * silu(g) -> half --------------
__global__ void gn_silu_kernel(const float* __restrict__ x, const float* __restrict__ g,
                               __half* __restrict__ out,
                               const float* __restrict__ s, const float* __restrict__ bb)
{
    int gid  = blockIdx.x*4 + (threadIdx.x >> 5);
    int lane = threadIdx.x & 31;
    int h    = gid % H_;
    int row  = gid / H_;

    const float* xp = x + (size_t)row*C_ + h*K_;
    float x0 = xp[lane], x1 = xp[lane+32];
    float sum = x0 + x1;
    #pragma unroll
    for (int o=16;o;o>>=1) sum += __shfl_xor_sync(0xffffffffu, sum, o);
    float m  = sum * (1.f/64.f);
    float d0 = x0-m, d1 = x1-m;
    float sq = d0*d0 + d1*d1;
    #pragma unroll
    for (int o=16;o;o>>=1) sq += __shfl_xor_sync(0xffffffffu, sq, o);
    float rstd = rsqrtf(sq*(1.f/64.f) + 0.00064f);

    int c0 = h*K_ + lane, c1 = c0 + 32;
    float y0 = fmaf(d0*rstd, s[c0], bb[c0]);
    float y1 = fmaf(d1*rstd, s[c1], bb[c1]);

    const float* gp = g + (size_t)row*C_ + h*K_;
    float g0 = gp[lane], g1 = gp[lane+32];
    y0 *= g0 / (1.f + expf(-g0));
    y1 *= g1 / (1.f + expf(-g1));

    __half* opp = out + (size_t)row*C_ + h*K_;
    opp[lane]    = __float2half_rn(y0);
    opp[lane+32] = __float2half_rn(y1);
}

// ---------------- orchestration --------------------------------------------
#define SMEM_BIG   (2*(128+128)*40*2)    // 40960 B
#define SMEM_SMALL (2*(64+64)*40*2)      // 20480 B

extern "C" void kernel_launch(void* const* d_in, const int* in_sizes, int n_in,
                              void* d_out, int out_size)
{
    (void)in_sizes; (void)n_in; (void)out_size;
    const int*   tokens    = (const int*)  d_in[0];
    const float* embed     = (const float*)d_in[1];
    const float* emb_ln_s  = (const float*)d_in[2];
    const float* emb_ln_b  = (const float*)d_in[3];
    const float* tm_ln_s   = (const float*)d_in[4];
    const float* tm_ln_b   = (const float*)d_in[5];
    const float* ts_r      = (const float*)d_in[6];
    const float* ts_k      = (const float*)d_in[7];
    const float* ts_v      = (const float*)d_in[8];
    const float* ts_g      = (const float*)d_in[9];
    const float* W_r       = (const float*)d_in[10];
    const float* W_k       = (const float*)d_in[11];
    const float* W_v       = (const float*)d_in[12];
    const float* W_g       = (const float*)d_in[13];
    const float* W_o       = (const float*)d_in[14];
    const float* bonus     = (const float*)d_in[15];
    const float* decay     = (const float*)d_in[16];
    const float* gn_s      = (const float*)d_in[17];
    const float* gn_b      = (const float*)d_in[18];
    const float* cm_ln_s   = (const float*)d_in[19];
    const float* cm_ln_b   = (const float*)d_in[20];
    const float* cm_ts_in  = (const float*)d_in[21];
    const float* cm_ts_g   = (const float*)d_in[22];
    const float* W_in      = (const float*)d_in[23];
    const float* W_out     = (const float*)d_in[24];
    const float* W_gate    = (const float*)d_in[25];
    const float* head_ln_s = (const float*)d_in[26];
    const float* head_ln_b = (const float*)d_in[27];
    const float* W_unembed = (const float*)d_in[28];

    __half *wh, *ah, *hidh, *gath;
    float *x, *ln, *part, *rkvg, *wkv, *gate;
    cudaGetSymbolAddress((void**)&wh,   g_wh);
    cudaGetSymbolAddress((void**)&x,    g_x);
    cudaGetSymbolAddress((void**)&ln,   g_ln);
    cudaGetSymbolAddress((void**)&ah,   g_ah);
    cudaGetSymbolAddress((void**)&hidh, g_hidh);
    cudaGetSymbolAddress((void**)&gath, g_gath);
    cudaGetSymbolAddress((void**)&part, g_part);
    cudaGetSymbolAddress((void**)&rkvg, g_rkvg);
    cudaGetSymbolAddress((void**)&wkv,  g_wkv);
    cudaGetSymbolAddress((void**)&gate, g_gate);

    // opt-in dynamic smem (idempotent)
    cudaFuncSetAttribute(hgemm<128,128,4,2,0,0,0>, cudaFuncAttributeMaxDynamicSharedMemorySize, SMEM_BIG);
    cudaFuncSetAttribute(hgemm<128,128,4,2,1,0,1>, cudaFuncAttributeMaxDynamicSharedMemorySize, SMEM_BIG);
    cudaFuncSetAttribute(hgemm<64,64,2,2,2,0,0>,   cudaFuncAttributeMaxDynamicSharedMemorySize, SMEM_SMALL);
    cudaFuncSetAttribute(hgemm<64,64,2,2,3,0,0>,   cudaFuncAttributeMaxDynamicSharedMemorySize, SMEM_SMALL);
    cudaFuncSetAttribute(hgemm<64,64,2,2,0,1,0>,   cudaFuncAttributeMaxDynamicSharedMemorySize, SMEM_SMALL);

    // ONE side stream (R13's proven resource footprint) + events
    cudaStream_t s2;
    cudaStreamCreateWithFlags(&s2, cudaStreamNonBlocking);
    auto fork_to_s2 = [&]() {
        cudaEvent_t e;
        cudaEventCreateWithFlags(&e, cudaEventDisableTiming);
        cudaEventRecord(e, 0);
        cudaStreamWaitEvent(s2, e, 0);
    };
    auto join_from_s2 = [&]() {
        cudaEvent_t e;
        cudaEventCreateWithFlags(&e, cudaEventDisableTiming);
        cudaEventRecord(e, s2);
        cudaStreamWaitEvent(0, e, 0);
    };

    // ---- weight conversion: a1 on default; a2+a3 on s2 (overlap layer 0) --
    {
        CvtArgs5 a1;
        a1.s[0] = { W_r,  OFF_WR,  CCL/8 };
        a1.s[1] = { W_k,  OFF_WK,  CCL/8 };
        a1.s[2] = { W_v,  OFF_WV,  CCL/8 };
        a1.s[3] = { W_g,  OFF_WG,  CCL/8 };
        a1.s[4] = { W_o,  OFF_WO,  CCL/8 };
        a1.n = 5;
        long tot1 = 5*(CCL/8);
        cvt_all_kernel<<<(int)((tot1 + 1023)/1024), 256>>>(a1, wh, tot1);
    }
    fork_to_s2();
    {
        CvtArgs5 a2;
        a2.s[0] = { W_in,   OFF_WIN,  FCL/8 };
        a2.s[1] = { W_out,  OFF_WOUT, FCL/8 };
        a2.s[2] = { W_gate, OFF_WGT,  CCL/8 };
        a2.n = 3;
        long tot2 = 2*(FCL/8) + CCL/8;
        cvt_all_kernel<<<(int)((tot2 + 1023)/1024), 256, 0, s2>>>(a2, wh, tot2);

        CvtArgs5 a3;
        a3.s[0] = { W_unembed, OFF_WUN, VCL/8 };
        a3.n = 1;
        long tot3 = VCL/8;
        cvt_all_kernel<<<(int)((tot3 + 1023)/1024), 256, 0, s2>>>(a3, wh, tot3);
    }

    const __half* cW_r  = wh + OFF_WR;
    const __half* cW_k  = wh + OFF_WK;
    const __half* cW_v  = wh + OFF_WV;
    const __half* cW_g  = wh + OFF_WG;
    const __half* cW_o  = wh + OFF_WO;
    const __half* cW_in = wh + OFF_WIN;
    const __half* cW_out= wh + OFF_WOUT;
    const __half* cW_gt = wh + OFF_WGT;
    const __half* cW_un = wh + OFF_WUN;

    const int EW_BLOCKS = (M_*C_ + 255)/256;

    // embedding gather + LN (residual base, fp32)
    ln_kernel<<<M_, 256>>>(embed, tokens, x, nullptr, emb_ln_s, emb_ln_b, 1e-5f);

    for (int l = 0; l < L_; l++) {
        size_t cc = (size_t)l*C_*C_;
        size_t fc = (size_t)l*DFF_*C_;
        size_t oc = (size_t)l*C_*DFF_;
        size_t hk = (size_t)l*H_*K_;

        // ---- time mixer ----
        ln_lerp_kernel<4><<<M_, 256>>>(x, tm_ln_s + l*C_, tm_ln_b + l*C_,
                                       ts_r + l*C_, ts_k + l*C_,
                                       ts_v + l*C_, ts_g + l*C_, ah);
        if (l == 0) {
            // s2 is busy converting channel-mix + unembed weights:
            // run r,k,v,g as one batched GEMM on the default stream.
            hgemm<128,128,4,2,0,0,0><<<dim3(C_/128, M_/128, 4), 128, SMEM_BIG>>>(
                ah, cW_r + cc, cW_k + cc, cW_v + cc, cW_g + cc, rkvg, nullptr,
                nullptr, nullptr, M_, C_, C_, C_);
        } else {
            // fork: g GEMM on s2 concurrently with the wkv scan
            fork_to_s2();
            hgemm<128,128,4,2,0,0,0><<<dim3(C_/128, M_/128, 1), 128, SMEM_BIG, s2>>>(
                ah + 3*(size_t)M_*C_, cW_g + cc, nullptr, nullptr, nullptr,
                rkvg + 3*(size_t)M_*C_, nullptr,
                nullptr, nullptr, M_, C_, C_, C_);
            hgemm<128,128,4,2,0,0,0><<<dim3(C_/128, M_/128, 3), 128, SMEM_BIG>>>(
                ah, cW_r + cc, cW_k + cc, cW_v + cc, cW_v + cc, rkvg, nullptr,
                nullptr, nullptr, M_, C_, C_, C_);
        }
        wkv_kernel<<<B_*H_*2, 256>>>(rkvg, rkvg + M_*C_, rkvg + 2*M_*C_, wkv,
                                     bonus + hk, decay + hk);
        if (l != 0) join_from_s2();   // g ready
        gn_silu_kernel<<<(M_*H_)/4, 128>>>(wkv, rkvg + 3*M_*C_, gath,
                                           gn_s + l*C_, gn_b + l*C_);
        hgemm<64,64,2,2,3,0,0><<<dim3(C_/64, M_/64, 1), 64, SMEM_SMALL>>>(
            gath, cW_o + cc, nullptr, nullptr, nullptr, x, nullptr,
            x, nullptr, M_, C_, C_, C_);

        // before layer-0 channel mixer: wait for a2 (and a3, FIFO) on s2
        if (l == 0) join_from_s2();

        // ---- channel mixer ----
        ln_lerp_kernel<2><<<M_, 256>>>(x, cm_ln_s + l*C_, cm_ln_b + l*C_,
                                       cm_ts_in + l*C_, cm_ts_g + l*C_,
                                       nullptr, nullptr, ah);
        // fork: Wgate on s2 concurrently with Win -> Wout chain
        fork_to_s2();
        hgemm<64,64,2,2,2,0,0><<<dim3(C_/64, M_/64, 1), 64, SMEM_SMALL, s2>>>(
            ah + M_*C_, cW_gt + cc, nullptr, nullptr, nullptr, gate, nullptr,
            nullptr, nullptr, M_, C_, C_, C_);
        hgemm<128,128,4,2,1,0,1><<<dim3(DFF_/128, M_/128, 1), 128, SMEM_BIG>>>(
            ah, cW_in + fc, nullptr, nullptr, nullptr, nullptr, hidh,
            nullptr, nullptr, M_, DFF_, C_, C_);
        // W_out: split-K = 4, partials, fused reduce*gate + residual
        hgemm<64,64,2,2,0,1,0><<<dim3(C_/64, M_/64, 4), 64, SMEM_SMALL>>>(
            hidh, cW_out + oc, nullptr, nullptr, nullptr, part, nullptr,
            nullptr, nullptr, M_, C_, DFF_/4, DFF_);
        join_from_s2();   // gate ready
        reduce4_gate_kernel<<<EW_BLOCKS, 256>>>(part, gate, x, M_*C_);
    }

    // head LN -> half, unembed (a3 already covered by the layer-0 join)
    ln_kernel<<<M_, 256>>>(x, nullptr, nullptr, ah, head_ln_s, head_ln_b, 1e-5f);
    hgemm<128,128,4,2,0,0,0><<<dim3(V_/128, M_/128, 1), 128, SMEM_BIG>>>(
        ah, cW_un, nullptr, nullptr, nullptr, (float*)d_out, nullptr,
        nullptr, nullptr, M_, V_, C_, C_);
}

// round 17
// speedup vs baseline: 1.0270x; 1.0270x over previous
#include <cuda_runtime.h>
#include <cuda_fp16.h>
#include <math.h>
#include <mma.h>
#include <cstdint>

using namespace nvcuda;

// Problem dims
#define B_   2
#define T_   512
#define C_   768
#define H_   12
#define K_   64
#define L_   6
#define DFF_ 2688
#define V_   50304
#define M_   (B_*T_)   // 1024 rows

// weight family sizes (elements)
#define CCL  ((long)L_*C_*C_)
#define FCL  ((long)L_*DFF_*C_)
#define VCL  ((long)V_*C_)

#define OFF_WR   0L
#define OFF_WK   (OFF_WR + CCL)
#define OFF_WV   (OFF_WK + CCL)
#define OFF_WG   (OFF_WV + CCL)
#define OFF_WO   (OFF_WG + CCL)
#define OFF_WIN  (OFF_WO + CCL)
#define OFF_WOUT (OFF_WIN + FCL)
#define OFF_WGT  (OFF_WOUT + FCL)
#define OFF_WUN  (OFF_WGT + CCL)
#define WTF_TOT  (OFF_WUN + VCL)

// ---------------- scratch (device globals; no allocation allowed) ----------
__device__ __half g_wh  [WTF_TOT];    // fp16 weights
__device__ float  g_x   [M_*C_];
__device__ float  g_ln  [M_*C_];
__device__ __half g_ah  [4*M_*C_];    // half activations
__device__ __half g_hidh[M_*DFF_];    // half hidden (relu^2 out)
__device__ __half g_gath[M_*C_];      // half gated (gn*silu out)
__device__ float  g_part[4*M_*C_];    // split-K partials
__device__ float  g_rkvg[4*M_*C_];
__device__ float  g_wkv [M_*C_];
__device__ float  g_gate[M_*C_];

// ---------------- helpers ---------------------------------------------------
__device__ __forceinline__ void cp_async16(void* smem_dst, const void* gsrc) {
    unsigned dst = (unsigned)__cvta_generic_to_shared(smem_dst);
    asm volatile("cp.async.cg.shared.global [%0], [%1], 16;\n" :: "r"(dst), "l"(gsrc));
}
__device__ __forceinline__ void cp_commit() { asm volatile("cp.async.commit_group;\n"); }
__device__ __forceinline__ void cp_wait1()  { asm volatile("cp.async.wait_group 1;\n"); }
__device__ __forceinline__ void cp_wait0()  { asm volatile("cp.async.wait_group 0;\n"); }

// ---------------- batched fp32 -> fp16 weight conversion -------------------
struct CvtSeg { const float* src; long dst_off; long n8; };
struct CvtArgs5 { CvtSeg s[5]; int n; };

__global__ void cvt_all_kernel(CvtArgs5 args, __half* __restrict__ dstbase, long total8)
{
    long base = (long)blockIdx.x*1024 + threadIdx.x;

    const float4* src4[4];
    uint4*        dst4[4];
    bool          ok[4];
    #pragma unroll
    for (int it = 0; it < 4; it++) {
        long gid = base + (long)it*256;
        ok[it] = (gid < total8);
        src4[it] = nullptr; dst4[it] = nullptr;
        if (ok[it]) {
            long rem = gid;
            #pragma unroll
            for (int s = 0; s < 5; s++) {
                if (s >= args.n) { ok[it] = false; break; }
                if (rem < args.s[s].n8) {
                    src4[it] = (const float4*)args.s[s].src + 2*rem;
                    dst4[it] = (uint4*)(dstbase + args.s[s].dst_off) + rem;
                    break;
                }
                rem -= args.s[s].n8;
            }
        }
    }

    float4 a[4], b[4];
    #pragma unroll
    for (int it = 0; it < 4; it++) {
        if (ok[it]) { a[it] = src4[it][0]; b[it] = src4[it][1]; }
    }
    #pragma unroll
    for (int it = 0; it < 4; it++) {
        if (!ok[it]) continue;
        __half2 h0 = __floats2half2_rn(a[it].x, a[it].y);
        __half2 h1 = __floats2half2_rn(a[it].z, a[it].w);
        __half2 h2 = __floats2half2_rn(b[it].x, b[it].y);
        __half2 h3 = __floats2half2_rn(b[it].z, b[it].w);
        uint4 o;
        o.x = *(uint32_t*)&h0; o.y = *(uint32_t*)&h1;
        o.z = *(uint32_t*)&h2; o.w = *(uint32_t*)&h3;
        *dst4[it] = o;
    }
}

// ---------------- FP16 wmma GEMM, BK=32, cp.async double-buffered ----------
// MINB = min blocks per SM (occupancy hint).
template<int BM, int BN, int WARPS, int WNW, int MINB, int EPI, int SPLITK, int HOUT>
__global__ void __launch_bounds__(WARPS*32, MINB)
hgemm(const __half* __restrict__ Abase,
      const __half* __restrict__ W0, const __half* __restrict__ W1,
      const __half* __restrict__ W2, const __half* __restrict__ W3,
      float* __restrict__ Cbase, __half* __restrict__ Chbase,
      const float* __restrict__ Res, const float* __restrict__ Gate,
      int M, int N, int Kseg, int lda)
{
    constexpr int NT  = WARPS*32;
    constexpr int BK  = 32;
    constexpr int LDT = 40;                    // halves; 80B rows
    extern __shared__ __align__(16) __half sh[];
    __half* As = sh;                           // [2][BM*LDT]
    __half* Bs = sh + 2*BM*LDT;                // [2][BN*LDT]
    __shared__ __align__(16) float Ep[(EPI >= 3 || HOUT) ? WARPS*256 : 8];

    int z = blockIdx.z;
    const __half* A;
    const __half* W;
    float*  C  = nullptr;
    __half* Ch = nullptr;
    if (SPLITK) {
        A = Abase + (size_t)z*Kseg;
        W = W0    + (size_t)z*Kseg;
        C = Cbase + (size_t)z*M*N;
    } else {
        A = Abase + (size_t)z*M*lda;
        W = W0;
        if (z == 1) W = W1; else if (z == 2) W = W2; else if (z == 3) W = W3;
        if (HOUT) Ch = Chbase + (size_t)z*M*N;
        else      C  = Cbase  + (size_t)z*M*N;
    }

    int bm = blockIdx.y*BM, bn = blockIdx.x*BN;
    int tid = threadIdx.x, warp = tid>>5, lane = tid&31;
    constexpr int WMW = WARPS / WNW;
    int wm = warp / WNW;
    int wn = warp % WNW;
    constexpr int WM = BM/WMW;
    constexpr int WN = BN/WNW;
    constexpr int MF = WM/16, NF = WN/16;

    wmma::fragment<wmma::accumulator,16,16,16,float> cf[MF][NF];
    #pragma unroll
    for (int i=0;i<MF;i++)
        #pragma unroll
        for (int j=0;j<NF;j++) wmma::fill_fragment(cf[i][j], 0.f);

    constexpr int A_CP = BM*(BK/8)/NT;
    constexpr int B_CP = BN*(BK/8)/NT;

    const int nK = Kseg / BK;

    auto issue_stage = [&](int stg, int kt) {
        int k0 = kt*BK;
        __half* as = As + stg*BM*LDT;
        __half* bs = Bs + stg*BN*LDT;
        #pragma unroll
        for (int i=0;i<A_CP;i++){
            int idx = tid + i*NT;
            int row = idx >> 2, c8 = idx & 3;
            cp_async16(&as[row*LDT + c8*8],
                       A + (size_t)(bm+row)*lda + k0 + c8*8);
        }
        #pragma unroll
        for (int i=0;i<B_CP;i++){
            int idx = tid + i*NT;
            int row = idx >> 2, c8 = idx & 3;
            cp_async16(&bs[row*LDT + c8*8],
                       W + (size_t)(bn+row)*lda + k0 + c8*8);
        }
        cp_commit();
    };

    issue_stage(0, 0);

    for (int kt = 0; kt < nK; kt++) {
        if (kt + 1 < nK) { issue_stage((kt+1)&1, kt+1); cp_wait1(); }
        else             { cp_wait0(); }
        __syncthreads();
        int stg = kt & 1;
        const __half* as = As + stg*BM*LDT;
        const __half* bs = Bs + stg*BN*LDT;
        #pragma unroll
        for (int kk=0; kk<BK; kk+=16) {
            wmma::fragment<wmma::matrix_a,16,16,16,__half,wmma::row_major> af[MF];
            #pragma unroll
            for (int i=0;i<MF;i++)
                wmma::load_matrix_sync(af[i], &as[(wm*WM + i*16)*LDT + kk], LDT);
            #pragma unroll
            for (int j=0;j<NF;j++) {
                wmma::fragment<wmma::matrix_b,16,16,16,__half,wmma::col_major> bf;
                wmma::load_matrix_sync(bf, &bs[(wn*WN + j*16)*LDT + kk], LDT);
                #pragma unroll
                for (int i=0;i<MF;i++)
                    wmma::mma_sync(cf[i][j], af[i], bf, cf[i][j]);
            }
        }
        __syncthreads();
    }

    // ---- epilogue ----
    #pragma unroll
    for (int i=0;i<MF;i++){
        #pragma unroll
        for (int j=0;j<NF;j++){
            int r0 = bm + wm*WM + i*16;
            int c0 = bn + wn*WN + j*16;
            if (!HOUT && EPI == 0) {
                wmma::store_matrix_sync(&C[(size_t)r0*N + c0], cf[i][j], N, wmma::mem_row_major);
            } else if (!HOUT && EPI == 2) {
                #pragma unroll
                for (int e=0;e<cf[i][j].num_elements;e++)
                    cf[i][j].x[e] = 1.f/(1.f + expf(-cf[i][j].x[e]));
                wmma::store_matrix_sync(&C[(size_t)r0*N + c0], cf[i][j], N, wmma::mem_row_major);
            } else {
                float* buf = &Ep[warp*256];
                wmma::store_matrix_sync(buf, cf[i][j], 16, wmma::mem_row_major);
                __syncwarp();
                #pragma unroll
                for (int e=0;e<8;e++){
                    int idx2 = lane*8 + e;
                    int rr = idx2>>4, cc2 = idx2&15;
                    size_t o = (size_t)(r0+rr)*N + (c0+cc2);
                    float v = buf[idx2];
                    if (EPI == 1) { v = fmaxf(v, 0.f); v = v*v; }
                    else if (EPI == 3) { v += Res[o]; }
                    else if (EPI == 4) { v = fmaf(v, Gate[o], Res[o]); }
                    if (HOUT) Ch[o] = __float2half_rn(v);
                    else      C[o]  = v;
                }
                __syncwarp();
            }
        }
    }
}

// ---------------- split-K reduce: x += (p0+p1+p2+p3) * gate ----------------
__global__ void reduce4_gate_kernel(const float* __restrict__ parts,
                                    const float* __restrict__ gate,
                                    float* __restrict__ x, int n)
{
    int idx = blockIdx.x*blockDim.x + threadIdx.x;
    if (idx >= n) return;
    float v = (parts[idx]               + parts[idx +   (size_t)n])
            + (parts[idx + 2*(size_t)n] + parts[idx + 3*(size_t)n]);
    x[idx] = fmaf(v, gate[idx], x[idx]);
}

// ---------------- plain LayerNorm (emb gather / head), single-pass stats ---
__global__ void ln_kernel(const float* __restrict__ in,
                          const int*   __restrict__ tokens,
                          float*       __restrict__ out,
                          __half*      __restrict__ hout,
                          const float* __restrict__ s,
                          const float* __restrict__ bia,
                          float eps)
{
    int row = blockIdx.x;
    const float* xp = tokens ? (in + (size_t)tokens[row]*C_)
                             : (in + (size_t)row*C_);
    int tid = threadIdx.x;
    float v0 = xp[tid], v1 = xp[tid+256], v2 = xp[tid+512];

    __shared__ float red1[8], red2[8];
    __shared__ float s_mean, s_rstd;

    float s1 = v0 + v1 + v2;
    float s2v = v0*v0 + v1*v1 + v2*v2;
    #pragma unroll
    for (int o=16;o;o>>=1) {
        s1  += __shfl_xor_sync(0xffffffffu, s1, o);
        s2v += __shfl_xor_sync(0xffffffffu, s2v, o);
    }
    if ((tid & 31) == 0) { red1[tid>>5] = s1; red2[tid>>5] = s2v; }
    __syncthreads();
    if (tid == 0) {
        float t1=0.f, t2=0.f;
        for (int i=0;i<8;i++) { t1 += red1[i]; t2 += red2[i]; }
        float m = t1*(1.f/C_);
        s_mean = m;
        s_rstd = rsqrtf(t2*(1.f/C_) - m*m + eps);
    }
    __syncthreads();
    float m  = s_mean, rs = s_rstd;
    float y0 = (v0-m)*rs*s[tid]     + bia[tid];
    float y1 = (v1-m)*rs*s[tid+256] + bia[tid+256];
    float y2 = (v2-m)*rs*s[tid+512] + bia[tid+512];
    if (hout) {
        __half* hp = hout + (size_t)row*C_;
        hp[tid]     = __float2half_rn(y0);
        hp[tid+256] = __float2half_rn(y1);
        hp[tid+512] = __float2half_rn(y2);
    } else {
        float* op = out + (size_t)row*C_;
        op[tid] = y0; op[tid+256] = y1; op[tid+512] = y2;
    }
}

// ---------------- fused LN + token-shift + N-way lerp, single-pass stats ---
template<int NOUT>
__global__ void ln_lerp_kernel(const float* __restrict__ x,
                               const float* __restrict__ s,
                               const float* __restrict__ bia,
                               const float* __restrict__ t0,
                               const float* __restrict__ t1,
                               const float* __restrict__ t2,
                               const float* __restrict__ t3,
                               __half* __restrict__ aout)
{
    int row = blockIdx.x;
    int t   = row % T_;
    int tid = threadIdx.x;                 // 256

    const float* xc = x + (size_t)row*C_;
    float c0 = xc[tid], c1 = xc[tid+256], c2 = xc[tid+512];
    float p0 = 0.f, p1 = 0.f, p2 = 0.f;
    if (t > 0) {
        const float* xq = xc - C_;
        p0 = xq[tid]; p1 = xq[tid+256]; p2 = xq[tid+512];
    }

    __shared__ float r1c[8], r2c[8], r1p[8], r2p[8];
    __shared__ float s_mc, s_rc, s_mp, s_rp;

    float sc  = c0 + c1 + c2;
    float qc  = c0*c0 + c1*c1 + c2*c2;
    float sp  = p0 + p1 + p2;
    float qp  = p0*p0 + p1*p1 + p2*p2;
    #pragma unroll
    for (int o=16;o;o>>=1) {
        sc += __shfl_xor_sync(0xffffffffu, sc, o);
        qc += __shfl_xor_sync(0xffffffffu, qc, o);
        sp += __shfl_xor_sync(0xffffffffu, sp, o);
        qp += __shfl_xor_sync(0xffffffffu, qp, o);
    }
    if ((tid & 31) == 0) {
        r1c[tid>>5] = sc; r2c[tid>>5] = qc;
        r1p[tid>>5] = sp; r2p[tid>>5] = qp;
    }
    __syncthreads();
    if (tid == 0) {
        float tsc=0.f, tqc=0.f, tsp=0.f, tqp=0.f;
        for (int i=0;i<8;i++) { tsc += r1c[i]; tqc += r2c[i];
                                tsp += r1p[i]; tqp += r2p[i]; }
        float mc = tsc*(1.f/C_), mp = tsp*(1.f/C_);
        s_mc = mc; s_mp = mp;
        s_rc = rsqrtf(tqc*(1.f/C_) - mc*mc + 1e-5f);
        s_rp = rsqrtf(tqp*(1.f/C_) - mp*mp + 1e-5f);
    }
    __syncthreads();
    float mc = s_mc, rc = s_rc, mp = s_mp, rp = s_rp;

    #pragma unroll
    for (int u = 0; u < 3; u++) {
        int c  = tid + u*256;
        float cv = (u==0)?c0:((u==1)?c1:c2);
        float pv = (u==0)?p0:((u==1)?p1:p2);
        float yc = (cv-mc)*rc*s[c] + bia[c];
        float yp = (t > 0) ? ((pv-mp)*rp*s[c] + bia[c]) : 0.f;
        float d  = yp - yc;
        size_t o = (size_t)row*C_ + c;
        aout[o]                       = __float2half_rn(fmaf(t0[c], d, yc));
        aout[o +   (size_t)M_*C_]     = __float2half_rn(fmaf(t1[c], d, yc));
        if (NOUT == 4) {
            aout[o + 2*(size_t)M_*C_] = __float2half_rn(fmaf(t2[c], d, yc));
            aout[o + 3*(size_t)M_*C_] = __float2half_rn(fmaf(t3[c], d, yc));
        }
    }
}

// ---------------- WKV scan: 256 thr, 8-way k-split, pair-unrolled ----------
__global__ void wkv_kernel(const float* __restrict__ r, const float* __restrict__ k,
                           const float* __restrict__ v, float* __restrict__ out,
                           const float* __restrict__ bonus, const float* __restrict__ decay)
{
    int blk  = blockIdx.x;
    int vs   = blk & 1;
    int h    = (blk >> 1) % H_;
    int b    = blk / (2*H_);
    int tid  = threadIdx.x;        // 256
    int kc   = tid & 7;
    int vloc = tid >> 3;           // 0..31
    int vg   = vs*32 + vloc;

    size_t off = (size_t)b*T_*C_ + (size_t)h*K_;
    const float* rp = r + off;
    const float* kp = k + off;
    const float* vp = v + off;
    float*       op = out + off;

    float u[8], w[8], st[8];
    #pragma unroll
    for (int i = 0; i < 8; i++) {
        int kk = kc*8 + i;
        u[i]  = bonus[h*K_ + kk];
        w[i]  = expf(-expf(decay[h*K_ + kk]));
        st[i] = 0.f;
    }

    __shared__ float shr[2][2][64], shk[2][2][64];

    {
        int seg = tid >> 6, idx = tid & 63;
        if      (seg == 0) shr[0][0][idx] = rp[idx];
        else if (seg == 1) shr[0][1][idx] = rp[C_ + idx];
        else if (seg == 2) shk[0][0][idx] = kp[idx];
        else               shk[0][1][idx] = kp[C_ + idx];
    }
    float vv0 = vp[vg];
    float vv1 = vp[C_ + vg];
    __syncthreads();

    const int NP = T_/2;
    for (int p = 0; p < NP; p++) {
        int cur = p & 1, nxt = cur ^ 1;
        int t0 = 2*p;

        float pre = 0.f, nv0 = 0.f, nv1 = 0.f;
        int seg = tid >> 6, idx = tid & 63;
        if (p + 1 < NP) {
            size_t oA = (size_t)(t0+2)*C_, oB = (size_t)(t0+3)*C_;
            if      (seg == 0) pre = rp[oA + idx];
            else if (seg == 1) pre = rp[oB + idx];
            else if (seg == 2) pre = kp[oA + idx];
            else               pre = kp[oB + idx];
            nv0 = vp[oA + vg];
            nv1 = vp[oB + vg];
        }

        {
            float acc0 = 0.f, acc1 = 0.f;
            #pragma unroll
            for (int i = 0; i < 8; i += 2) {
                float k0 = shk[cur][0][kc*8 + i]     * vv0;
                float k1 = shk[cur][0][kc*8 + i + 1] * vv0;
                acc0  = fmaf(shr[cur][0][kc*8 + i],     fmaf(u[i],   k0, st[i]),   acc0);
                acc1  = fmaf(shr[cur][0][kc*8 + i + 1], fmaf(u[i+1], k1, st[i+1]), acc1);
                st[i]   = fmaf(st[i],   w[i],   k0);
                st[i+1] = fmaf(st[i+1], w[i+1], k1);
            }
            float acc = acc0 + acc1;
            acc += __shfl_xor_sync(0xffffffffu, acc, 1);
            acc += __shfl_xor_sync(0xffffffffu, acc, 2);
            acc += __shfl_xor_sync(0xffffffffu, acc, 4);
            if (kc == 0) op[(size_t)t0*C_ + vg] = acc;
        }
        {
            float acc0 = 0.f, acc1 = 0.f;
            #pragma unroll
            for (int i = 0; i < 8; i += 2) {
                float k0 = shk[cur][1][kc*8 + i]     * vv1;
                float k1 = shk[cur][1][kc*8 + i + 1] * vv1;
                acc0  = fmaf(shr[cur][1][kc*8 + i],     fmaf(u[i],   k0, st[i]),   acc0);
                acc1  = fmaf(shr[cur][1][kc*8 + i + 1], fmaf(u[i+1], k1, st[i+1]), acc1);
                st[i]   = fmaf(st[i],   w[i],   k0);
                st[i+1] = fmaf(st[i+1], w[i+1], k1);
            }
            float acc = acc0 + acc1;
            acc += __shfl_xor_sync(0xffffffffu, acc, 1);
            acc += __shfl_xor_sync(0xffffffffu, acc, 2);
            acc += __shfl_xor_sync(0xffffffffu, acc, 4);
            if (kc == 0) op[(size_t)(t0+1)*C_ + vg] = acc;
        }

        if (p + 1 < NP) {
            if      (seg == 0) shr[nxt][0][idx] = pre;
            else if (seg == 1) shr[nxt][1][idx] = pre;
            else if (seg == 2) shk[nxt][0][idx] = pre;
            else               shk[nxt][1][idx] = pre;
            vv0 = nv0; vv1 = nv1;
        }
        __syncthreads();
    }
}

// ---------------- GroupNorm(H groups of 64) * silu(g) -> half --------------
__global__ void gn_silu_kernel(const float* __restrict__ x, const float* __restrict__ g,
                               __half* __restrict__ out,
                               const float* __restrict__ s, const float* __restrict__ bb)
{
    int gid  = blockIdx.x*4 + (threadIdx.x >> 5);
    int lane = threadIdx.x & 31;
    int h    = gid % H_;
    int row  = gid / H_;

    const float* xp = x + (size_t)row*C_ + h*K_;
    float x0 = xp[lane], x1 = xp[lane+32];
    float sum = x0 + x1;
    #pragma unroll
    for (int o=16;o;o>>=1) sum += __shfl_xor_sync(0xffffffffu, sum, o);
    float m  = sum * (1.f/64.f);
    float d0 = x0-m, d1 = x1-m;
    float sq = d0*d0 + d1*d1;
    #pragma unroll
    for (int o=16;o;o>>=1) sq += __shfl_xor_sync(0xffffffffu, sq, o);
    float rstd = rsqrtf(sq*(1.f/64.f) + 0.00064f);

    int c0 = h*K_ + lane, c1 = c0 + 32;
    float y0 = fmaf(d0*rstd, s[c0], bb[c0]);
    float y1 = fmaf(d1*rstd, s[c1], bb[c1]);

    const float* gp = g + (size_t)row*C_ + h*K_;
    float g0 = gp[lane], g1 = gp[lane+32];
    y0 *= g0 / (1.f + expf(-g0));
    y1 *= g1 / (1.f + expf(-g1));

    __half* opp = out + (size_t)row*C_ + h*K_;
    opp[lane]    = __float2half_rn(y0);
    opp[lane+32] = __float2half_rn(y1);
}

// ---------------- orchestration --------------------------------------------
#define SMEM_UN    (2*(128+128)*40*2)    // 40960 B (unembed, 128x128)
#define SMEM_MED   (2*(128+64)*40*2)     // 30720 B (rkvg/Win, 128x64)
#define SMEM_SMALL (2*(64+64)*40*2)      // 20480 B

extern "C" void kernel_launch(void* const* d_in, const int* in_sizes, int n_in,
                              void* d_out, int out_size)
{
    (void)in_sizes; (void)n_in; (void)out_size;
    const int*   tokens    = (const int*)  d_in[0];
    const float* embed     = (const float*)d_in[1];
    const float* emb_ln_s  = (const float*)d_in[2];
    const float* emb_ln_b  = (const float*)d_in[3];
    const float* tm_ln_s   = (const float*)d_in[4];
    const float* tm_ln_b   = (const float*)d_in[5];
    const float* ts_r      = (const float*)d_in[6];
    const float* ts_k      = (const float*)d_in[7];
    const float* ts_v      = (const float*)d_in[8];
    const float* ts_g      = (const float*)d_in[9];
    const float* W_r       = (const float*)d_in[10];
    const float* W_k       = (const float*)d_in[11];
    const float* W_v       = (const float*)d_in[12];
    const float* W_g       = (const float*)d_in[13];
    const float* W_o       = (const float*)d_in[14];
    const float* bonus     = (const float*)d_in[15];
    const float* decay     = (const float*)d_in[16];
    const float* gn_s      = (const float*)d_in[17];
    const float* gn_b      = (const float*)d_in[18];
    const float* cm_ln_s   = (const float*)d_in[19];
    const float* cm_ln_b   = (const float*)d_in[20];
    const float* cm_ts_in  = (const float*)d_in[21];
    const float* cm_ts_g   = (const float*)d_in[22];
    const float* W_in      = (const float*)d_in[23];
    const float* W_out     = (const float*)d_in[24];
    const float* W_gate    = (const float*)d_in[25];
    const float* head_ln_s = (const float*)d_in[26];
    const float* head_ln_b = (const float*)d_in[27];
    const float* W_unembed = (const float*)d_in[28];

    __half *wh, *ah, *hidh, *gath;
    float *x, *ln, *part, *rkvg, *wkv, *gate;
    cudaGetSymbolAddress((void**)&wh,   g_wh);
    cudaGetSymbolAddress((void**)&x,    g_x);
    cudaGetSymbolAddress((void**)&ln,   g_ln);
    cudaGetSymbolAddress((void**)&ah,   g_ah);
    cudaGetSymbolAddress((void**)&hidh, g_hidh);
    cudaGetSymbolAddress((void**)&gath, g_gath);
    cudaGetSymbolAddress((void**)&part, g_part);
    cudaGetSymbolAddress((void**)&rkvg, g_rkvg);
    cudaGetSymbolAddress((void**)&wkv,  g_wkv);
    cudaGetSymbolAddress((void**)&gate, g_gate);

    // opt-in dynamic smem (idempotent)
    cudaFuncSetAttribute(hgemm<128,128,4,2,2,0,0,0>, cudaFuncAttributeMaxDynamicSharedMemorySize, SMEM_UN);
    cudaFuncSetAttribute(hgemm<128,64,4,2,3,0,0,0>,  cudaFuncAttributeMaxDynamicSharedMemorySize, SMEM_MED);
    cudaFuncSetAttribute(hgemm<128,64,4,2,3,1,0,1>,  cudaFuncAttributeMaxDynamicSharedMemorySize, SMEM_MED);
    cudaFuncSetAttribute(hgemm<64,64,2,2,6,2,0,0>,   cudaFuncAttributeMaxDynamicSharedMemorySize, SMEM_SMALL);
    cudaFuncSetAttribute(hgemm<64,64,2,2,6,3,0,0>,   cudaFuncAttributeMaxDynamicSharedMemorySize, SMEM_SMALL);
    cudaFuncSetAttribute(hgemm<64,64,2,2,6,0,1,0>,   cudaFuncAttributeMaxDynamicSharedMemorySize, SMEM_SMALL);

    // ONE side stream + events (R13's proven resource footprint)
    cudaStream_t s2;
    cudaStreamCreateWithFlags(&s2, cudaStreamNonBlocking);
    auto fork_to_s2 = [&]() {
        cudaEvent_t e;
        cudaEventCreateWithFlags(&e, cudaEventDisableTiming);
        cudaEventRecord(e, 0);
        cudaStreamWaitEvent(s2, e, 0);
    };
    auto join_from_s2 = [&]() {
        cudaEvent_t e;
        cudaEventCreateWithFlags(&e, cudaEventDisableTiming);
        cudaEventRecord(e, s2);
        cudaStreamWaitEvent(0, e, 0);
    };

    // ---- fp16 conversion of all weights in 2 launches (R13 scheme) ----
    {
        CvtArgs5 a1;
        a1.s[0] = { W_r,  OFF_WR,  CCL/8 };
        a1.s[1] = { W_k,  OFF_WK,  CCL/8 };
        a1.s[2] = { W_v,  OFF_WV,  CCL/8 };
        a1.s[3] = { W_g,  OFF_WG,  CCL/8 };
        a1.s[4] = { W_o,  OFF_WO,  CCL/8 };
        a1.n = 5;
        long tot1 = 5*(CCL/8);
        cvt_all_kernel<<<(int)((tot1 + 1023)/1024), 256>>>(a1, wh, tot1);

        CvtArgs5 a2;
        a2.s[0] = { W_in,      OFF_WIN,  FCL/8 };
        a2.s[1] = { W_out,     OFF_WOUT, FCL/8 };
        a2.s[2] = { W_gate,    OFF_WGT,  CCL/8 };
        a2.s[3] = { W_unembed, OFF_WUN,  VCL/8 };
        a2.n = 4;
        long tot2 = 2*(FCL/8) + CCL/8 + VCL/8;
        cvt_all_kernel<<<(int)((tot2 + 1023)/1024), 256>>>(a2, wh, tot2);
    }

    const __half* cW_r  = wh + OFF_WR;
    const __half* cW_k  = wh + OFF_WK;
    const __half* cW_v  = wh + OFF_WV;
    const __half* cW_g  = wh + OFF_WG;
    const __half* cW_o  = wh + OFF_WO;
    const __half* cW_in = wh + OFF_WIN;
    const __half* cW_out= wh + OFF_WOUT;
    const __half* cW_gt = wh + OFF_WGT;
    const __half* cW_un = wh + OFF_WUN;

    const int EW_BLOCKS = (M_*C_ + 255)/256;

    // embedding gather + LN (residual base, fp32)
    ln_kernel<<<M_, 256>>>(embed, tokens, x, nullptr, emb_ln_s, emb_ln_b, 1e-5f);

    for (int l = 0; l < L_; l++) {
        size_t cc = (size_t)l*C_*C_;
        size_t fc = (size_t)l*DFF_*C_;
        size_t oc = (size_t)l*C_*DFF_;
        size_t hk = (size_t)l*H_*K_;

        // ---- time mixer ----
        ln_lerp_kernel<4><<<M_, 256>>>(x, tm_ln_s + l*C_, tm_ln_b + l*C_,
                                       ts_r + l*C_, ts_k + l*C_,
                                       ts_v + l*C_, ts_g + l*C_, ah);
        // fork: g GEMM on s2 concurrently with the wkv scan
        fork_to_s2();
        hgemm<128,64,4,2,3,0,0,0><<<dim3(C_/64, M_/128, 1), 128, SMEM_MED, s2>>>(
            ah + 3*(size_t)M_*C_, cW_g + cc, nullptr, nullptr, nullptr,
            rkvg + 3*(size_t)M_*C_, nullptr,
            nullptr, nullptr, M_, C_, C_, C_);
        // r,k,v on default stream (z = 3 batches)
        hgemm<128,64,4,2,3,0,0,0><<<dim3(C_/64, M_/128, 3), 128, SMEM_MED>>>(
            ah, cW_r + cc, cW_k + cc, cW_v + cc, cW_v + cc, rkvg, nullptr,
            nullptr, nullptr, M_, C_, C_, C_);
        wkv_kernel<<<B_*H_*2, 256>>>(rkvg, rkvg + M_*C_, rkvg + 2*M_*C_, wkv,
                                     bonus + hk, decay + hk);
        join_from_s2();   // g ready
        gn_silu_kernel<<<(M_*H_)/4, 128>>>(wkv, rkvg + 3*M_*C_, gath,
                                           gn_s + l*C_, gn_b + l*C_);
        hgemm<64,64,2,2,6,3,0,0><<<dim3(C_/64, M_/64, 1), 64, SMEM_SMALL>>>(
            gath, cW_o + cc, nullptr, nullptr, nullptr, x, nullptr,
            x, nullptr, M_, C_, C_, C_);

        // ---- channel mixer ----
        ln_lerp_kernel<2><<<M_, 256>>>(x, cm_ln_s + l*C_, cm_ln_b + l*C_,
                                       cm_ts_in + l*C_, cm_ts_g + l*C_,
                                       nullptr, nullptr, ah);
        // fork: Wgate on s2 concurrently with Win -> Wout chain
        fork_to_s2();
        hgemm<64,64,2,2,6,2,0,0><<<dim3(C_/64, M_/64, 1), 64, SMEM_SMALL, s2>>>(
            ah + M_*C_, cW_gt + cc, nullptr, nullptr, nullptr, gate, nullptr,
            nullptr, nullptr, M_, C_, C_, C_);
        hgemm<128,64,4,2,3,1,0,1><<<dim3(DFF_/64, M_/128, 1), 128, SMEM_MED>>>(
            ah, cW_in + fc, nullptr, nullptr, nullptr, nullptr, hidh,
            nullptr, nullptr, M_, DFF_, C_, C_);
        // W_out: split-K = 4, partials, fused reduce*gate + residual
        hgemm<64,64,2,2,6,0,1,0><<<dim3(C_/64, M_/64, 4), 64, SMEM_SMALL>>>(
            hidh, cW_out + oc, nullptr, nullptr, nullptr, part, nullptr,
            nullptr, nullptr, M_, C_, DFF_/4, DFF_);
        join_from_s2();   // gate ready
        reduce4_gate_kernel<<<EW_BLOCKS, 256>>>(part, gate, x, M_*C_);
    }

    // head LN -> half, unembed (128x128 tiles: grid fills the chip)
    ln_kernel<<<M_, 256>>>(x, nullptr, nullptr, ah, head_ln_s, head_ln_b, 1e-5f);
    hgemm<128,128,4,2,2,0,0,0><<<dim3(V_/128, M_/128, 1), 128, SMEM_UN>>>(
        ah, cW_un, nullptr, nullptr, nullptr, (float*)d_out, nullptr,
        nullptr, nullptr, M_, V_, C_, C_);
}